// round 5
// baseline (speedup 1.0000x reference)
#include <cuda_runtime.h>
#include <math.h>
#include <stdint.h>

#define B_  64
#define T_  512
#define IN_ 1024
#define H_  1024
#define L_  5

#define NBLK 128   // persistent CTAs, 1 per SM
#define TPB  256   // 8 warps

typedef unsigned long long ull;

// Static device scratch:
__device__ float g_xw[(size_t)B_ * T_ * 2 * H_];   // [whx|wtx], time-major
__device__ float g_state[2][B_ * H_];              // double-buffered state
__device__ unsigned g_bar_arrive = 0;
__device__ unsigned g_bar_gen    = 0;

// ---- packed fp32x2 helpers (sm_103a FFMA2) --------------------------------
__device__ __forceinline__ void ffma2(ull& d, ull a, ull b) {
    asm("fma.rn.f32x2 %0, %1, %2, %0;" : "+l"(d) : "l"(a), "l"(b));
}
__device__ __forceinline__ ull packff(float x, float y) {
    ull r; asm("mov.b64 %0, {%1, %2};" : "=l"(r) : "f"(x), "f"(y)); return r;
}
__device__ __forceinline__ float f32x2_sum(ull v) {
    union { ull u; float2 f; } c; c.u = v; return c.f.x + c.f.y;
}

// ---- cp.async helpers -----------------------------------------------------
__device__ __forceinline__ void cp16_cg(uint32_t dst, const void* src) {
    asm volatile("cp.async.cg.shared.global [%0], [%1], 16;" :: "r"(dst), "l"(src) : "memory");
}
__device__ __forceinline__ void cp16_ca(uint32_t dst, const void* src) {
    asm volatile("cp.async.ca.shared.global [%0], [%1], 16;" :: "r"(dst), "l"(src) : "memory");
}
#define CP_COMMIT() asm volatile("cp.async.commit_group;" ::: "memory")
#define CP_WAIT0()  asm volatile("cp.async.wait_group 0;" ::: "memory")
#define CP_WAIT1()  asm volatile("cp.async.wait_group 1;" ::: "memory")

// smem geometry (dynamic)
#define SS_PITCH 132
#define SS_BUF   (64 * SS_PITCH)            // one state buffer
#define SW_BUF   (16 * SS_PITCH)            // one weight buffer (2 gates x 8 rows)
#define SMEM_FLOATS (2 * SS_BUF + 2 * SW_BUF)

// ---------------------------------------------------------------------------
// Input GEMM with FFMA2: C[r][j] = sum_k x[row(r)][k] * W[k][j]
// ---------------------------------------------------------------------------
__global__ __launch_bounds__(256) void xw_gemm_kernel(
    const float* __restrict__ x,
    const float* __restrict__ w_h,
    const float* __restrict__ w_t)
{
    __shared__ float As[8][132];
    __shared__ float Bs[8][132];

    const int jb  = blockIdx.x;
    const int rb  = blockIdx.y;
    const int tid = threadIdx.x;
    const int tx  = tid % 16;
    const int ty  = tid / 16;

    const int jbase = jb * 128;
    const float* W  = (jbase < H_) ? w_h : w_t;
    const int  joff = jbase % H_;

    ull acc2[8][4];
    #pragma unroll
    for (int i = 0; i < 8; i++)
        #pragma unroll
        for (int j = 0; j < 4; j++) acc2[i][j] = 0ull;

    const int arow = tid / 2;
    const int ak   = (tid % 2) * 4;
    const int r    = rb * 128 + arow;
    const int xrow = (r % B_) * T_ + (r / B_);
    const float* aptr = x + (size_t)xrow * IN_ + ak;

    const int bk = tid / 32;
    const int bj = (tid % 32) * 4;
    const float* bptr = W + (size_t)bk * H_ + joff + bj;

    for (int kt = 0; kt < IN_; kt += 8) {
        float4 av = *(const float4*)(aptr + kt);
        float4 bv = *(const float4*)(bptr + (size_t)kt * H_);
        __syncthreads();
        As[ak + 0][arow] = av.x;
        As[ak + 1][arow] = av.y;
        As[ak + 2][arow] = av.z;
        As[ak + 3][arow] = av.w;
        *(float4*)&Bs[bk][bj] = bv;
        __syncthreads();

        #pragma unroll
        for (int k = 0; k < 8; k++) {
            float a[8];
            #pragma unroll
            for (int i = 0; i < 8; i++) a[i] = As[k][ty * 8 + i];
            ulonglong2 bv0 = *(const ulonglong2*)&Bs[k][tx * 8];
            ulonglong2 bv1 = *(const ulonglong2*)&Bs[k][tx * 8 + 4];
            #pragma unroll
            for (int i = 0; i < 8; i++) {
                ull ap = packff(a[i], a[i]);
                ffma2(acc2[i][0], ap, bv0.x);
                ffma2(acc2[i][1], ap, bv0.y);
                ffma2(acc2[i][2], ap, bv1.x);
                ffma2(acc2[i][3], ap, bv1.y);
            }
        }
    }

    #pragma unroll
    for (int i = 0; i < 8; i++) {
        int rr = rb * 128 + ty * 8 + i;
        float* cp = g_xw + (size_t)rr * (2 * H_) + jbase + tx * 8;
        union { ull u; float2 f; } c0, c1, c2, c3;
        c0.u = acc2[i][0]; c1.u = acc2[i][1]; c2.u = acc2[i][2]; c3.u = acc2[i][3];
        *(float4*)(cp + 0) = make_float4(c0.f.x, c0.f.y, c1.f.x, c1.f.y);
        *(float4*)(cp + 4) = make_float4(c2.f.x, c2.f.y, c3.f.x, c3.f.y);
    }
}

// ---------------------------------------------------------------------------
// Grid-wide barrier for co-resident persistent CTAs.
// ---------------------------------------------------------------------------
__device__ __forceinline__ void grid_sync_persistent()
{
    __syncthreads();
    if (threadIdx.x == 0) {
        volatile unsigned* genp = &g_bar_gen;
        unsigned my_gen = *genp;
        __threadfence();
        unsigned a = atomicAdd(&g_bar_arrive, 1u);
        if (a == NBLK - 1) {
            g_bar_arrive = 0;
            __threadfence();
            atomicAdd(&g_bar_gen, 1u);   // release
        } else {
            while (*genp == my_gen) { }
            __threadfence();
        }
    }
    __syncthreads();
}

// ---------------------------------------------------------------------------
// Persistent recurrent kernel: 2560 micro-steps, cp.async double-buffered.
// 128 blocks x 256 threads. Block owns 8 g-columns of BOTH gates.
// Thread: 2 b-rows x 1 g x 2 gates, packed f32x2 accumulation.
// ---------------------------------------------------------------------------
__global__ __launch_bounds__(TPB) void rhn_persistent_kernel(
    const float* __restrict__ rh_w, const float* __restrict__ rh_b,
    const float* __restrict__ rt_w, const float* __restrict__ rt_b,
    float* __restrict__ out)
{
    extern __shared__ float smem[];
    float* s_s = smem;                       // [2][64][SS_PITCH]
    float* s_w = smem + 2 * SS_BUF;          // [2][2][8][SS_PITCH]

    const uint32_t ss_u32 = (uint32_t)__cvta_generic_to_shared(s_s);
    const uint32_t sw_u32 = (uint32_t)__cvta_generic_to_shared(s_w);

    const int tid = threadIdx.x;
    const int gq  = tid & 7;
    const int bq  = tid >> 3;
    const int b0  = 2 * bq;
    const int b1  = 2 * bq + 1;
    const int r0   = tid >> 5;               // 0..7
    const int col4 = (tid & 31) * 4;         // 0..124
    const int gb  = blockIdx.x;
    const int g   = gb * 8 + gq;

    const float* whbase = rh_w + (size_t)(gb * 8) * H_;
    const float* wtbase = rt_w + (size_t)(gb * 8) * H_;

    // copy-issue helpers (lambdas keep indices in registers)
    auto issue_w = [&](const float* wh, const float* wt, int kt, int buf) {
        const int kbase = kt * 128 + col4;
        cp16_ca(sw_u32 + (uint32_t)((buf * 16 + r0) * SS_PITCH + col4) * 4,
                wh + (size_t)r0 * H_ + kbase);
        cp16_ca(sw_u32 + (uint32_t)((buf * 16 + 8 + r0) * SS_PITCH + col4) * 4,
                wt + (size_t)r0 * H_ + kbase);
    };
    auto issue_s = [&](const float* scur, int kt, int buf) {
        const int kbase = kt * 128 + col4;
        #pragma unroll
        for (int i = 0; i < 8; i++)
            cp16_cg(ss_u32 + (uint32_t)((buf * 64 + r0 + 8 * i) * SS_PITCH + col4) * 4,
                    scur + (size_t)(r0 + 8 * i) * H_ + kbase);
    };

    // prologue: tile 0 of step 0 into buffer 0
    {
        const float* sc0 = g_state[0];
        issue_w(whbase, wtbase, 0, 0);
        issue_s(sc0, 0, 0);
        CP_COMMIT();
    }

    int t = 0, l = 0;
    for (int step = 0; step < T_ * L_; step++) {
        const int pin = step & 1;
        const float* scur = g_state[pin];
        float*       snxt = g_state[pin ^ 1];
        const float* wh = whbase + (size_t)l * H_ * H_;
        const float* wt = wtbase + (size_t)l * H_ * H_;

        // hoisted epilogue operands (hide L2 latency behind the mainloop)
        const float so0 = scur[(size_t)b0 * H_ + g];
        const float so1 = scur[(size_t)b1 * H_ + g];
        const float bh  = rh_b[l * H_ + g];
        const float bt  = rt_b[l * H_ + g];
        float xh0 = 0.f, xt0 = 0.f, xh1 = 0.f, xt1 = 0.f;
        if (l == 0) {
            const float* xw0 = g_xw + (size_t)(t * B_ + b0) * (2 * H_);
            const float* xw1 = g_xw + (size_t)(t * B_ + b1) * (2 * H_);
            xh0 = xw0[g];  xt0 = xw0[H_ + g];
            xh1 = xw1[g];  xt1 = xw1[H_ + g];
        }

        ull aH0 = 0ull, aH1 = 0ull, aT0 = 0ull, aT1 = 0ull;

        for (int kt = 0; kt < 8; kt++) {
            if (kt < 7) {
                issue_w(wh, wt, kt + 1, (kt + 1) & 1);
                issue_s(scur, kt + 1, (kt + 1) & 1);
                CP_COMMIT();
                CP_WAIT1();          // tile kt finished
            } else {
                CP_WAIT0();
            }
            __syncthreads();         // all threads' copies visible

            const int cur = kt & 1;
            const float* sb0 = s_s + cur * SS_BUF + b0 * SS_PITCH;
            const float* sb1 = s_s + cur * SS_BUF + b1 * SS_PITCH;
            const float* wHp = s_w + cur * SW_BUF + gq * SS_PITCH;
            const float* wTp = s_w + cur * SW_BUF + (8 + gq) * SS_PITCH;

            #pragma unroll
            for (int k4 = 0; k4 < 32; k4++) {
                ulonglong2 sv0 = *(const ulonglong2*)(sb0 + k4 * 4);
                ulonglong2 sv1 = *(const ulonglong2*)(sb1 + k4 * 4);
                ulonglong2 wHv = *(const ulonglong2*)(wHp + k4 * 4);
                ulonglong2 wTv = *(const ulonglong2*)(wTp + k4 * 4);
                ffma2(aH0, sv0.x, wHv.x);
                ffma2(aH1, sv1.x, wHv.x);
                ffma2(aT0, sv0.x, wTv.x);
                ffma2(aT1, sv1.x, wTv.x);
                ffma2(aH0, sv0.y, wHv.y);
                ffma2(aH1, sv1.y, wHv.y);
                ffma2(aT0, sv0.y, wTv.y);
                ffma2(aT1, sv1.y, wTv.y);
            }
            __syncthreads();         // compute done before buffer reuse
        }

        // epilogue
        float ph0 = f32x2_sum(aH0) + bh + xh0;
        float ph1 = f32x2_sum(aH1) + bh + xh1;
        float pt0 = f32x2_sum(aT0) + bt + xt0;
        float pt1 = f32x2_sum(aT1) + bt + xt1;

        const float h0  = tanhf(ph0);
        const float h1  = tanhf(ph1);
        const float tt0 = 1.0f / (1.0f + expf(-pt0));
        const float tt1 = 1.0f / (1.0f + expf(-pt1));
        const float sn0 = fmaf(h0 - so0, tt0, so0);
        const float sn1 = fmaf(h1 - so1, tt1, so1);
        snxt[(size_t)b0 * H_ + g] = sn0;
        snxt[(size_t)b1 * H_ + g] = sn1;
        if (l == L_ - 1) {
            out[((size_t)b0 * T_ + t) * H_ + g] = sn0;
            out[((size_t)b1 * T_ + t) * H_ + g] = sn1;
            if (t == T_ - 1) {
                out[(size_t)B_ * T_ * H_ + (size_t)b0 * H_ + g] = sn0;
                out[(size_t)B_ * T_ * H_ + (size_t)b1 * H_ + g] = sn1;
            }
        }

        if (++l == L_) { l = 0; ++t; }

        if (step != T_ * L_ - 1) {
            // pre-issue next step's WEIGHT tile 0 (read-only: safe pre-barrier)
            const float* whn = whbase + (size_t)l * H_ * H_;
            const float* wtn = wtbase + (size_t)l * H_ * H_;
            issue_w(whn, wtn, 0, 0);

            grid_sync_persistent();

            // state for next step is now published; stream its tile 0
            issue_s(g_state[(step + 1) & 1], 0, 0);
            CP_COMMIT();
        }
    }
}

// ---------------------------------------------------------------------------
extern "C" void kernel_launch(void* const* d_in, const int* in_sizes, int n_in,
                              void* d_out, int out_size)
{
    const float* input = (const float*)d_in[0];
    const float* s0    = (const float*)d_in[1];
    const float* w_h   = (const float*)d_in[2];
    const float* w_t   = (const float*)d_in[3];
    const float* rh_w  = (const float*)d_in[4];
    const float* rh_b  = (const float*)d_in[5];
    const float* rt_w  = (const float*)d_in[6];
    const float* rt_b  = (const float*)d_in[7];
    float* out = (float*)d_out;

    static bool attr_set = false;
    if (!attr_set) {
        cudaFuncSetAttribute(rhn_persistent_kernel,
                             cudaFuncAttributeMaxDynamicSharedMemorySize,
                             SMEM_FLOATS * sizeof(float));
        attr_set = true;
    }

    cudaMemcpyToSymbolAsync(g_state, s0, (size_t)B_ * H_ * sizeof(float), 0,
                            cudaMemcpyDeviceToDevice);

    {
        dim3 grid(16, 256);
        xw_gemm_kernel<<<grid, 256>>>(input, w_h, w_t);
    }

    rhn_persistent_kernel<<<NBLK, TPB, SMEM_FLOATS * sizeof(float)>>>(
        rh_w, rh_b, rt_w, rt_b, out);
}